// round 1
// baseline (speedup 1.0000x reference)
#include <cuda_runtime.h>
#include <cuda_bf16.h>

#define Nn  150000
#define Ee  600000
#define FIN 32
#define Hh  128
#define Gg  2048

// ---------------- scratch (device globals; no allocation allowed) ----------
__device__ float g_agg[Nn * Hh];
__device__ float g_t1 [Nn * Hh];
__device__ float g_t2 [Nn * Hh];
__device__ float g_h  [Nn * Hh];
__device__ float g_pool[Gg * Hh];
__device__ float g_cnt [Gg];
__device__ float g_hd1 [Gg * Hh];
__device__ float g_hd2 [Gg * Hh];

// ---------------- simple vector copy (agg := h, the "+x" of GIN) ----------
__global__ void copy_k(float4* __restrict__ dst, const float4* __restrict__ src, int n4) {
    int i = blockIdx.x * blockDim.x + threadIdx.x;
    if (i < n4) dst[i] = src[i];
}

// ---------------- edge scatter-add: agg[dst] += h[src] ---------------------
template<int K>
__global__ void scatter_k(float* __restrict__ agg, const float* __restrict__ h,
                          const int* __restrict__ ei) {
    const int C = K / 4;                 // float4 chunks per row
    int idx = blockIdx.x * blockDim.x + threadIdx.x;
    if (idx >= Ee * C) return;
    int e = idx / C;
    int c = idx - e * C;
    int s = ei[e];
    int d = ei[Ee + e];
    float4 v = reinterpret_cast<const float4*>(h)[s * C + c];
    float* dst = agg + d * K + c * 4;
    atomicAdd(dst + 0, v.x);
    atomicAdd(dst + 1, v.y);
    atomicAdd(dst + 2, v.z);
    atomicAdd(dst + 3, v.w);
}

// ---------------- fused GEMM + bias + (optional) ReLU ----------------------
// C[M,128] = act(A[M,K] @ W[K,128] + b)
// Block: 128 threads. Tile: 64 rows x 128 cols. Per-thread 8x8 micro-tile.
template<int K, bool RELU>
__global__ __launch_bounds__(128)
void gemm_k(const float* __restrict__ A, const float* __restrict__ W,
            const float* __restrict__ bias, float* __restrict__ C, int M) {
    const int KC = 16;
    __shared__ float As[KC][68];     // [k][m], padded (68*4=272 bytes, 16B-aligned rows)
    __shared__ float Ws[KC][128];    // [k][n]

    int tid = threadIdx.x;
    int tx  = tid & 15;              // n-group: cols tx*8 .. tx*8+7
    int ty  = tid >> 4;              // m-group: rows ty*8 .. ty*8+7
    int m0  = blockIdx.x * 64;

    float acc[8][8];
#pragma unroll
    for (int i = 0; i < 8; i++)
#pragma unroll
        for (int j = 0; j < 8; j++) acc[i][j] = 0.f;

    for (int kc = 0; kc < K; kc += KC) {
        // load A tile (64 x 16), transposed into As[k][m]
#pragma unroll
        for (int i = 0; i < 2; i++) {
            int li  = tid * 2 + i;          // 0..255
            int row = li >> 2;
            int c4  = li & 3;
            int m   = m0 + row;
            float4 v = make_float4(0.f, 0.f, 0.f, 0.f);
            if (m < M) v = *reinterpret_cast<const float4*>(&A[m * K + kc + c4 * 4]);
            As[c4 * 4 + 0][row] = v.x;
            As[c4 * 4 + 1][row] = v.y;
            As[c4 * 4 + 2][row] = v.z;
            As[c4 * 4 + 3][row] = v.w;
        }
        // load W tile (16 x 128)
#pragma unroll
        for (int i = 0; i < 4; i++) {
            int li = i * 128 + tid;         // 0..511
            int k  = li >> 5;
            int n4 = li & 31;
            *reinterpret_cast<float4*>(&Ws[k][n4 * 4]) =
                *reinterpret_cast<const float4*>(&W[(kc + k) * Hh + n4 * 4]);
        }
        __syncthreads();

#pragma unroll
        for (int k = 0; k < KC; k++) {
            float4 a0 = *reinterpret_cast<const float4*>(&As[k][ty * 8]);
            float4 a1 = *reinterpret_cast<const float4*>(&As[k][ty * 8 + 4]);
            float4 w0 = *reinterpret_cast<const float4*>(&Ws[k][tx * 8]);
            float4 w1 = *reinterpret_cast<const float4*>(&Ws[k][tx * 8 + 4]);
            float a[8] = {a0.x, a0.y, a0.z, a0.w, a1.x, a1.y, a1.z, a1.w};
            float w[8] = {w0.x, w0.y, w0.z, w0.w, w1.x, w1.y, w1.z, w1.w};
#pragma unroll
            for (int i = 0; i < 8; i++)
#pragma unroll
                for (int j = 0; j < 8; j++) acc[i][j] += a[i] * w[j];
        }
        __syncthreads();
    }

    float b[8];
#pragma unroll
    for (int j = 0; j < 8; j++) b[j] = bias[tx * 8 + j];

#pragma unroll
    for (int i = 0; i < 8; i++) {
        int m = m0 + ty * 8 + i;
        if (m < M) {
            float o[8];
#pragma unroll
            for (int j = 0; j < 8; j++) {
                float v = acc[i][j] + b[j];
                o[j] = RELU ? fmaxf(v, 0.f) : v;
            }
            *reinterpret_cast<float4*>(&C[m * Hh + tx * 8])     = make_float4(o[0], o[1], o[2], o[3]);
            *reinterpret_cast<float4*>(&C[m * Hh + tx * 8 + 4]) = make_float4(o[4], o[5], o[6], o[7]);
        }
    }
}

// ---------------- pooling ---------------------------------------------------
__global__ void zero_k(float* p, int n) {
    int i = blockIdx.x * blockDim.x + threadIdx.x;
    if (i < n) p[i] = 0.f;
}

__global__ void pool_k(const float* __restrict__ h, const int* __restrict__ batch,
                       float* __restrict__ pool) {
    int idx = blockIdx.x * blockDim.x + threadIdx.x;
    if (idx >= Nn * Hh) return;
    int n = idx >> 7;
    int f = idx & 127;
    atomicAdd(&pool[batch[n] * Hh + f], h[idx]);
}

__global__ void cnt_k(const int* __restrict__ batch, float* __restrict__ cnt) {
    int n = blockIdx.x * blockDim.x + threadIdx.x;
    if (n < Nn) atomicAdd(&cnt[batch[n]], 1.f);
}

__global__ void div_k(float* __restrict__ pool, const float* __restrict__ cnt) {
    int idx = blockIdx.x * blockDim.x + threadIdx.x;
    if (idx >= Gg * Hh) return;
    pool[idx] *= 1.f / fmaxf(cnt[idx >> 7], 1.f);
}

// ---------------- output head ----------------------------------------------
__global__ void out_k(const float* __restrict__ g2, const float* __restrict__ ow,
                      const float* __restrict__ ob, float* __restrict__ out) {
    int g = blockIdx.x * blockDim.x + threadIdx.x;
    if (g >= Gg) return;
    float s0 = ob[0], s1 = ob[1];
#pragma unroll 4
    for (int k = 0; k < Hh; k++) {
        float v = g2[g * Hh + k];
        s0 += v * ow[k * 2 + 0];
        s1 += v * ow[k * 2 + 1];
    }
    out[g * 2 + 0] = s0;
    out[g * 2 + 1] = s1;
}

// ---------------- launch -----------------------------------------------------
extern "C" void kernel_launch(void* const* d_in, const int* in_sizes, int n_in,
                              void* d_out, int out_size) {
    const float* x     = (const float*)d_in[0];
    const int*   ei    = (const int*)  d_in[1];
    const int*   batch = (const int*)  d_in[2];
    // per-layer weights: index 3 + 6*L
    const float* w1[3], *b1[3], *w2[3], *b2[3], *w3[3], *b3[3];
    for (int L = 0; L < 3; L++) {
        w1[L] = (const float*)d_in[3 + 6 * L + 0];
        b1[L] = (const float*)d_in[3 + 6 * L + 1];
        w2[L] = (const float*)d_in[3 + 6 * L + 2];
        b2[L] = (const float*)d_in[3 + 6 * L + 3];
        w3[L] = (const float*)d_in[3 + 6 * L + 4];
        b3[L] = (const float*)d_in[3 + 6 * L + 5];
    }
    const float* fc0w = (const float*)d_in[21];
    const float* fc0b = (const float*)d_in[22];
    const float* fc1w = (const float*)d_in[23];
    const float* fc1b = (const float*)d_in[24];
    const float* outw = (const float*)d_in[25];
    const float* outb = (const float*)d_in[26];

    float *agg, *t1, *t2, *h, *pool, *cnt, *hd1, *hd2;
    cudaGetSymbolAddress((void**)&agg,  g_agg);
    cudaGetSymbolAddress((void**)&t1,   g_t1);
    cudaGetSymbolAddress((void**)&t2,   g_t2);
    cudaGetSymbolAddress((void**)&h,    g_h);
    cudaGetSymbolAddress((void**)&pool, g_pool);
    cudaGetSymbolAddress((void**)&cnt,  g_cnt);
    cudaGetSymbolAddress((void**)&hd1,  g_hd1);
    cudaGetSymbolAddress((void**)&hd2,  g_hd2);

    const int TB = 256;
    int gemm_grid = (Nn + 63) / 64;

    // -------- layer 0 (K = 32 input features) --------
    {
        int n4 = Nn * FIN / 4;
        copy_k<<<(n4 + TB - 1) / TB, TB>>>((float4*)agg, (const float4*)x, n4);
        int nt = Ee * (FIN / 4);
        scatter_k<FIN><<<(nt + TB - 1) / TB, TB>>>(agg, x, ei);
        gemm_k<FIN, true><<<gemm_grid, 128>>>(agg, w1[0], b1[0], t1, Nn);
        gemm_k<Hh,  true><<<gemm_grid, 128>>>(t1,  w2[0], b2[0], t2, Nn);
        gemm_k<Hh,  true><<<gemm_grid, 128>>>(t2,  w3[0], b3[0], h,  Nn);
    }
    // -------- layers 1, 2 (K = 128) --------
    for (int L = 1; L < 3; L++) {
        int n4 = Nn * Hh / 4;
        copy_k<<<(n4 + TB - 1) / TB, TB>>>((float4*)agg, (const float4*)h, n4);
        int nt = Ee * (Hh / 4);
        scatter_k<Hh><<<(nt + TB - 1) / TB, TB>>>(agg, h, ei);
        gemm_k<Hh, true><<<gemm_grid, 128>>>(agg, w1[L], b1[L], t1, Nn);
        gemm_k<Hh, true><<<gemm_grid, 128>>>(t1,  w2[L], b2[L], t2, Nn);
        gemm_k<Hh, true><<<gemm_grid, 128>>>(t2,  w3[L], b3[L], h,  Nn);
    }

    // -------- global mean pool --------
    zero_k<<<(Gg * Hh + TB - 1) / TB, TB>>>(pool, Gg * Hh);
    zero_k<<<(Gg + TB - 1) / TB, TB>>>(cnt, Gg);
    pool_k<<<(Nn * Hh + TB - 1) / TB, TB>>>(h, batch, pool);
    cnt_k<<<(Nn + TB - 1) / TB, TB>>>(batch, cnt);
    div_k<<<(Gg * Hh + TB - 1) / TB, TB>>>(pool, cnt);

    // -------- classifier head --------
    int head_grid = (Gg + 63) / 64;
    gemm_k<Hh, true><<<head_grid, 128>>>(pool, fc0w, fc0b, hd1, Gg);
    gemm_k<Hh, true><<<head_grid, 128>>>(hd1,  fc1w, fc1b, hd2, Gg);
    out_k<<<(Gg + 127) / 128, 128>>>(hd2, outw, outb, (float*)d_out);
}

// round 3
// speedup vs baseline: 1.3187x; 1.3187x over previous
#include <cuda_runtime.h>
#include <cuda_bf16.h>
#include <cstdint>

#define Nn  150000
#define Ee  600000
#define FIN 32
#define Hh  128
#define Gg  2048

// ---------------- scratch (device globals) ----------------------------------
__device__ float g_agg[Nn * Hh];
__device__ float g_t1 [Nn * Hh];   // bf16 pair view: hi at [0], lo at [Nn*Hh]
__device__ float g_t2 [Nn * Hh];
__device__ float g_h  [Nn * Hh];
__device__ float g_pool[Gg * Hh];
__device__ float g_cnt [Gg];
__device__ float g_hd1 [Gg * Hh];  // bf16 pair view
__device__ float g_hd2 [Gg * Hh];
// 11 weight slots: slot0 = 32x128, slots1..10 = 128x128 (transposed to [n][k])
#define WTOT (4096 + 10 * 16384)
__device__ __nv_bfloat16 g_wth[WTOT];
__device__ __nv_bfloat16 g_wtl[WTOT];

// ---------------- helpers -----------------------------------------------------
__device__ __forceinline__ uint32_t smem_u32(const void* p) {
    uint32_t a;
    asm("{ .reg .u64 t; cvta.to.shared.u64 t, %1; cvt.u32.u64 %0, t; }" : "=r"(a) : "l"(p));
    return a;
}

__device__ __forceinline__ void ldsm4(uint32_t (&r)[4], uint32_t addr) {
    asm volatile("ldmatrix.sync.aligned.m8n8.x4.shared.b16 {%0,%1,%2,%3}, [%4];"
                 : "=r"(r[0]), "=r"(r[1]), "=r"(r[2]), "=r"(r[3]) : "r"(addr));
}

__device__ __forceinline__ void mma16816(float (&c)[4], const uint32_t (&a)[4],
                                         uint32_t b0, uint32_t b1) {
    asm volatile(
        "mma.sync.aligned.m16n8k16.row.col.f32.bf16.bf16.f32 "
        "{%0,%1,%2,%3},{%4,%5,%6,%7},{%8,%9},{%0,%1,%2,%3};"
        : "+f"(c[0]), "+f"(c[1]), "+f"(c[2]), "+f"(c[3])
        : "r"(a[0]), "r"(a[1]), "r"(a[2]), "r"(a[3]), "r"(b0), "r"(b1));
}

__device__ __forceinline__ void split2(float a, float b, uint32_t& hv, uint32_t& lv) {
    __nv_bfloat16 ha = __float2bfloat16(a), hb = __float2bfloat16(b);
    float la = a - __bfloat162float(ha), lb = b - __bfloat162float(hb);
    __nv_bfloat162 hp = __halves2bfloat162(ha, hb);     // .x = low = a
    __nv_bfloat162 lp = __floats2bfloat162_rn(la, lb);
    hv = *reinterpret_cast<uint32_t*>(&hp);
    lv = *reinterpret_cast<uint32_t*>(&lp);
}

// ---------------- split-bf16 HMMA GEMM ----------------------------------------
// D[M,128] = ReLU(A[M,K] @ W[K,128] + bias) via Ahi*Bhi + Ahi*Blo + Alo*Bhi
// IN: 0 = fp32 A,  1 = fp32 A + fp32 A2 (fused GIN add),  2 = pre-split bf16 pair
// OUT: 0 = fp32,   1 = split bf16 pair
template<int K, int IN, int OUT>
__global__ __launch_bounds__(256)
void mma_gemm(const float* __restrict__ A, const float* __restrict__ A2,
              const __nv_bfloat16* __restrict__ Ahg, const __nv_bfloat16* __restrict__ Alg,
              const __nv_bfloat16* __restrict__ Bh, const __nv_bfloat16* __restrict__ Bl,
              const float* __restrict__ bias,
              float* __restrict__ C, __nv_bfloat16* __restrict__ Ch, __nv_bfloat16* __restrict__ Cl,
              int M) {
    constexpr int PITCH = K + 8;                 // bf16 units per smem row
    constexpr int TILEB = 128 * PITCH * 2;       // bytes per tile
    extern __shared__ char smem[];

    int tid = threadIdx.x, lane = tid & 31, wid = tid >> 5;
    int m0 = blockIdx.x * 128;

    // ---- fill A tiles (hi at 0, lo at TILEB) ----
    if (IN == 2) {
        constexpr int CH = K / 8;                // 8-col (16B) chunks per row
        constexpr int ITER = 128 * CH / 256;
#pragma unroll
        for (int it = 0; it < ITER; it++) {
            int l = tid + it * 256;
            int row = l / CH, col = (l % CH) * 8;
            uint4 hv = make_uint4(0, 0, 0, 0), lv = make_uint4(0, 0, 0, 0);
            int m = m0 + row;
            if (m < M) {
                hv = *reinterpret_cast<const uint4*>(Ahg + (size_t)m * K + col);
                lv = *reinterpret_cast<const uint4*>(Alg + (size_t)m * K + col);
            }
            *reinterpret_cast<uint4*>(smem + (row * PITCH + col) * 2)         = hv;
            *reinterpret_cast<uint4*>(smem + TILEB + (row * PITCH + col) * 2) = lv;
        }
    } else {
        constexpr int CH = K / 4;                // 4-col fp32 chunks
        constexpr int ITER = 128 * CH / 256;
#pragma unroll
        for (int it = 0; it < ITER; it++) {
            int l = tid + it * 256;
            int row = l / CH, col = (l % CH) * 4;
            float4 v = make_float4(0.f, 0.f, 0.f, 0.f);
            int m = m0 + row;
            if (m < M) {
                v = *reinterpret_cast<const float4*>(A + (size_t)m * K + col);
                if (IN == 1) {
                    float4 w = *reinterpret_cast<const float4*>(A2 + (size_t)m * K + col);
                    v.x += w.x; v.y += w.y; v.z += w.z; v.w += w.w;
                }
            }
            uint32_t h0, l0, h1, l1;
            split2(v.x, v.y, h0, l0);
            split2(v.z, v.w, h1, l1);
            *reinterpret_cast<uint2*>(smem + (row * PITCH + col) * 2)         = make_uint2(h0, h1);
            *reinterpret_cast<uint2*>(smem + TILEB + (row * PITCH + col) * 2) = make_uint2(l0, l1);
        }
    }
    // ---- fill B tiles (hi at 2*TILEB, lo at 3*TILEB); B is [n=128][k=K] ----
    {
        constexpr int CH = K / 8;
        constexpr int ITER = 128 * CH / 256;
#pragma unroll
        for (int it = 0; it < ITER; it++) {
            int l = tid + it * 256;
            int row = l / CH, col = (l % CH) * 8;
            uint4 hv = *reinterpret_cast<const uint4*>(Bh + row * K + col);
            uint4 lv = *reinterpret_cast<const uint4*>(Bl + row * K + col);
            *reinterpret_cast<uint4*>(smem + 2 * TILEB + (row * PITCH + col) * 2) = hv;
            *reinterpret_cast<uint4*>(smem + 3 * TILEB + (row * PITCH + col) * 2) = lv;
        }
    }
    __syncthreads();

    // ---- warp tiles: warp_m in {0,1} (64 rows), warp_n in {0..3} (32 cols) ----
    int warp_m = wid & 1, warp_n = wid >> 1;
    float acc[4][4][4];
#pragma unroll
    for (int i = 0; i < 4; i++)
#pragma unroll
        for (int j = 0; j < 4; j++)
#pragma unroll
            for (int k = 0; k < 4; k++) acc[i][j][k] = 0.f;

    uint32_t sb = smem_u32(smem);
    int a_r = lane & 15;
    int a_c = (lane & 16) ? 8 : 0;
    int b_r = (lane & 7) + ((lane & 16) ? 8 : 0);
    int b_c = (lane & 8) ? 8 : 0;

#pragma unroll
    for (int kk = 0; kk < K / 16; kk++) {
        uint32_t ah[4][4], al[4][4], bh[2][4], bl[2][4];
#pragma unroll
        for (int mt = 0; mt < 4; mt++) {
            uint32_t off = (uint32_t)(((warp_m * 64 + mt * 16 + a_r) * PITCH + kk * 16 + a_c) * 2);
            ldsm4(ah[mt], sb + off);
            ldsm4(al[mt], sb + TILEB + off);
        }
#pragma unroll
        for (int p = 0; p < 2; p++) {
            uint32_t off = (uint32_t)(((warp_n * 32 + p * 16 + b_r) * PITCH + kk * 16 + b_c) * 2);
            ldsm4(bh[p], sb + 2 * TILEB + off);
            ldsm4(bl[p], sb + 3 * TILEB + off);
        }
#pragma unroll
        for (int mt = 0; mt < 4; mt++)
#pragma unroll
            for (int nt = 0; nt < 4; nt++) {
                int p = nt >> 1, q = (nt & 1) * 2;
                mma16816(acc[mt][nt], ah[mt], bh[p][q], bh[p][q + 1]);
                mma16816(acc[mt][nt], ah[mt], bl[p][q], bl[p][q + 1]);
                mma16816(acc[mt][nt], al[mt], bh[p][q], bh[p][q + 1]);
            }
    }

    // ---- epilogue: bias + ReLU, write fp32 or split pair ----
    int qrow = lane >> 2, qcol = (lane & 3) * 2;
#pragma unroll
    for (int mt = 0; mt < 4; mt++) {
        int r0 = m0 + warp_m * 64 + mt * 16 + qrow;
        int r1 = r0 + 8;
#pragma unroll
        for (int nt = 0; nt < 4; nt++) {
            int col = warp_n * 32 + nt * 8 + qcol;
            float bs0 = __ldg(bias + col), bs1 = __ldg(bias + col + 1);
            float o0 = fmaxf(acc[mt][nt][0] + bs0, 0.f);
            float o1 = fmaxf(acc[mt][nt][1] + bs1, 0.f);
            float o2 = fmaxf(acc[mt][nt][2] + bs0, 0.f);
            float o3 = fmaxf(acc[mt][nt][3] + bs1, 0.f);
            if (OUT == 0) {
                if (r0 < M) *reinterpret_cast<float2*>(C + (size_t)r0 * 128 + col) = make_float2(o0, o1);
                if (r1 < M) *reinterpret_cast<float2*>(C + (size_t)r1 * 128 + col) = make_float2(o2, o3);
            } else {
                uint32_t h0, l0, h1, l1;
                split2(o0, o1, h0, l0);
                split2(o2, o3, h1, l1);
                if (r0 < M) {
                    *reinterpret_cast<uint32_t*>(Ch + (size_t)r0 * 128 + col) = h0;
                    *reinterpret_cast<uint32_t*>(Cl + (size_t)r0 * 128 + col) = l0;
                }
                if (r1 < M) {
                    *reinterpret_cast<uint32_t*>(Ch + (size_t)r1 * 128 + col) = h1;
                    *reinterpret_cast<uint32_t*>(Cl + (size_t)r1 * 128 + col) = l1;
                }
            }
        }
    }
}

// ---------------- weight prep: all 11 slots in one launch ---------------------
struct WP { const float* p[11]; };

__global__ void prep_all(WP wp, __nv_bfloat16* __restrict__ hi, __nv_bfloat16* __restrict__ lo) {
    int slot = blockIdx.x >> 7;
    int n = blockIdx.x & 127;
    int K = (slot == 0) ? FIN : Hh;
    size_t off = (slot == 0) ? 0 : (size_t)4096 + (size_t)(slot - 1) * 16384;
    const float* W = wp.p[slot];
    for (int k = threadIdx.x; k < K; k += blockDim.x) {
        float v = W[k * Hh + n];
        __nv_bfloat16 h = __float2bfloat16(v);
        hi[off + (size_t)n * K + k] = h;
        lo[off + (size_t)n * K + k] = __float2bfloat16(v - __bfloat162float(h));
    }
}

// ---------------- graph ops (unchanged from round 1) ---------------------------
__global__ void zero_k(float* p, int n) {
    int i = blockIdx.x * blockDim.x + threadIdx.x;
    if (i < n) p[i] = 0.f;
}

template<int K>
__global__ void scatter_k(float* __restrict__ agg, const float* __restrict__ h,
                          const int* __restrict__ ei) {
    const int C = K / 4;
    int idx = blockIdx.x * blockDim.x + threadIdx.x;
    if (idx >= Ee * C) return;
    int e = idx / C;
    int c = idx - e * C;
    int s = ei[e];
    int d = ei[Ee + e];
    float4 v = reinterpret_cast<const float4*>(h)[s * C + c];
    float* dst = agg + (size_t)d * K + c * 4;
    atomicAdd(dst + 0, v.x);
    atomicAdd(dst + 1, v.y);
    atomicAdd(dst + 2, v.z);
    atomicAdd(dst + 3, v.w);
}

__global__ void pool_k(const float* __restrict__ h, const int* __restrict__ batch,
                       float* __restrict__ pool) {
    int idx = blockIdx.x * blockDim.x + threadIdx.x;
    if (idx >= Nn * Hh) return;
    int n = idx >> 7, f = idx & 127;
    atomicAdd(&pool[batch[n] * Hh + f], h[idx]);
}

__global__ void cnt_k(const int* __restrict__ batch, float* __restrict__ cnt) {
    int n = blockIdx.x * blockDim.x + threadIdx.x;
    if (n < Nn) atomicAdd(&cnt[batch[n]], 1.f);
}

__global__ void div_k(float* __restrict__ pool, const float* __restrict__ cnt) {
    int idx = blockIdx.x * blockDim.x + threadIdx.x;
    if (idx >= Gg * Hh) return;
    pool[idx] *= 1.f / fmaxf(cnt[idx >> 7], 1.f);
}

__global__ void out_k(const float* __restrict__ g2, const float* __restrict__ ow,
                      const float* __restrict__ ob, float* __restrict__ out) {
    int g = blockIdx.x * blockDim.x + threadIdx.x;
    if (g >= Gg) return;
    float s0 = ob[0], s1 = ob[1];
#pragma unroll 4
    for (int k = 0; k < Hh; k++) {
        float v = g2[g * Hh + k];
        s0 += v * ow[k * 2 + 0];
        s1 += v * ow[k * 2 + 1];
    }
    out[g * 2 + 0] = s0;
    out[g * 2 + 1] = s1;
}

// ---------------- launch -------------------------------------------------------
extern "C" void kernel_launch(void* const* d_in, const int* in_sizes, int n_in,
                              void* d_out, int out_size) {
    const float* x     = (const float*)d_in[0];
    const int*   ei    = (const int*)  d_in[1];
    const int*   batch = (const int*)  d_in[2];
    const float* b1[3], *b2[3], *b3[3];
    WP wp;
    for (int L = 0; L < 3; L++) {
        wp.p[3 * L + 0] = (const float*)d_in[3 + 6 * L + 0];   // w1
        b1[L]           = (const float*)d_in[3 + 6 * L + 1];
        wp.p[3 * L + 1] = (const float*)d_in[3 + 6 * L + 2];   // w2
        b2[L]           = (const float*)d_in[3 + 6 * L + 3];
        wp.p[3 * L + 2] = (const float*)d_in[3 + 6 * L + 4];   // w3
        b3[L]           = (const float*)d_in[3 + 6 * L + 5];
    }
    wp.p[9]  = (const float*)d_in[21];   // fc0_w
    const float* fc0b = (const float*)d_in[22];
    wp.p[10] = (const float*)d_in[23];   // fc1_w
    const float* fc1b = (const float*)d_in[24];
    const float* outw = (const float*)d_in[25];
    const float* outb = (const float*)d_in[26];

    float *agg, *t1, *t2, *h, *pool, *cnt, *hd1, *hd2;
    __nv_bfloat16 *wth, *wtl;
    cudaGetSymbolAddress((void**)&agg,  g_agg);
    cudaGetSymbolAddress((void**)&t1,   g_t1);
    cudaGetSymbolAddress((void**)&t2,   g_t2);
    cudaGetSymbolAddress((void**)&h,    g_h);
    cudaGetSymbolAddress((void**)&pool, g_pool);
    cudaGetSymbolAddress((void**)&cnt,  g_cnt);
    cudaGetSymbolAddress((void**)&hd1,  g_hd1);
    cudaGetSymbolAddress((void**)&hd2,  g_hd2);
    cudaGetSymbolAddress((void**)&wth,  g_wth);
    cudaGetSymbolAddress((void**)&wtl,  g_wtl);

    __nv_bfloat16* t1h = (__nv_bfloat16*)t1;  __nv_bfloat16* t1l = t1h + (size_t)Nn * Hh;
    __nv_bfloat16* t2h = (__nv_bfloat16*)t2;  __nv_bfloat16* t2l = t2h + (size_t)Nn * Hh;
    __nv_bfloat16* h1h = (__nv_bfloat16*)hd1; __nv_bfloat16* h1l = h1h + (size_t)Gg * Hh;

    auto woff = [](int s) -> size_t { return s == 0 ? 0 : (size_t)4096 + (size_t)(s - 1) * 16384; };

    const int SM32  = 4 * 128 * (FIN + 8) * 2;   // 40960
    const int SM128 = 4 * 128 * (Hh + 8) * 2;    // 139264
    cudaFuncSetAttribute(mma_gemm<FIN, 1, 1>, cudaFuncAttributeMaxDynamicSharedMemorySize, SM32);
    cudaFuncSetAttribute(mma_gemm<Hh, 1, 1>,  cudaFuncAttributeMaxDynamicSharedMemorySize, SM128);
    cudaFuncSetAttribute(mma_gemm<Hh, 2, 1>,  cudaFuncAttributeMaxDynamicSharedMemorySize, SM128);
    cudaFuncSetAttribute(mma_gemm<Hh, 2, 0>,  cudaFuncAttributeMaxDynamicSharedMemorySize, SM128);
    cudaFuncSetAttribute(mma_gemm<Hh, 0, 1>,  cudaFuncAttributeMaxDynamicSharedMemorySize, SM128);

    const int TB = 256;
    int ggrid = (Nn + 127) / 128;   // 1172
    int hgrid = (Gg + 127) / 128;   // 16

    prep_all<<<11 * 128, 128>>>(wp, wth, wtl);

    // ---- layer 0 (K = 32) ----
    zero_k<<<(Nn * FIN + TB - 1) / TB, TB>>>(agg, Nn * FIN);
    scatter_k<FIN><<<(Ee * (FIN / 4) + TB - 1) / TB, TB>>>(agg, x, ei);
    mma_gemm<FIN, 1, 1><<<ggrid, 256, SM32>>>(agg, x, nullptr, nullptr,
                                              wth + woff(0), wtl + woff(0), b1[0],
                                              nullptr, t1h, t1l, Nn);
    mma_gemm<Hh, 2, 1><<<ggrid, 256, SM128>>>(nullptr, nullptr, t1h, t1l,
                                              wth + woff(1), wtl + woff(1), b2[0],
                                              nullptr, t2h, t2l, Nn);
    mma_gemm<Hh, 2, 0><<<ggrid, 256, SM128>>>(nullptr, nullptr, t2h, t2l,
                                              wth + woff(2), wtl + woff(2), b3[0],
                                              h, nullptr, nullptr, Nn);

    // ---- layers 1, 2 (K = 128) ----
    for (int L = 1; L < 3; L++) {
        zero_k<<<(Nn * Hh + TB - 1) / TB, TB>>>(agg, Nn * Hh);
        scatter_k<Hh><<<(Ee * (Hh / 4) + TB - 1) / TB, TB>>>(agg, h, ei);
        mma_gemm<Hh, 1, 1><<<ggrid, 256, SM128>>>(agg, h, nullptr, nullptr,
                                                  wth + woff(3 * L), wtl + woff(3 * L), b1[L],
                                                  nullptr, t1h, t1l, Nn);
        mma_gemm<Hh, 2, 1><<<ggrid, 256, SM128>>>(nullptr, nullptr, t1h, t1l,
                                                  wth + woff(3 * L + 1), wtl + woff(3 * L + 1), b2[L],
                                                  nullptr, t2h, t2l, Nn);
        mma_gemm<Hh, 2, 0><<<ggrid, 256, SM128>>>(nullptr, nullptr, t2h, t2l,
                                                  wth + woff(3 * L + 2), wtl + woff(3 * L + 2), b3[L],
                                                  h, nullptr, nullptr, Nn);
    }

    // ---- global mean pool ----
    zero_k<<<(Gg * Hh + TB - 1) / TB, TB>>>(pool, Gg * Hh);
    zero_k<<<(Gg + TB - 1) / TB, TB>>>(cnt, Gg);
    pool_k<<<(Nn * Hh + TB - 1) / TB, TB>>>(h, batch, pool);
    cnt_k<<<(Nn + TB - 1) / TB, TB>>>(batch, cnt);
    div_k<<<(Gg * Hh + TB - 1) / TB, TB>>>(pool, cnt);

    // ---- classifier head ----
    mma_gemm<Hh, 0, 1><<<hgrid, 256, SM128>>>(pool, nullptr, nullptr, nullptr,
                                              wth + woff(9), wtl + woff(9), fc0b,
                                              nullptr, h1h, h1l, Gg);
    mma_gemm<Hh, 2, 0><<<hgrid, 256, SM128>>>(nullptr, nullptr, h1h, h1l,
                                              wth + woff(10), wtl + woff(10), fc1b,
                                              hd2, nullptr, nullptr, Gg);
    out_k<<<(Gg + 127) / 128, 128>>>(hd2, outw, outb, (float*)d_out);
}

// round 4
// speedup vs baseline: 1.6730x; 1.2686x over previous
#include <cuda_runtime.h>
#include <cuda_bf16.h>
#include <cstdint>

#define Nn  150000
#define Ee  600000
#define FIN 32
#define Hh  128
#define Gg  2048

// ---------------- scratch (device globals) ----------------------------------
__device__ float g_agg[Nn * Hh];
__device__ float g_h  [Nn * Hh];
__device__ float g_pool[Gg * Hh];
__device__ float g_cnt [Gg];
__device__ float g_hd2 [Gg * Hh];
#define WTOT (4096 + 10 * 16384)
__device__ __nv_bfloat16 g_wth[WTOT];
__device__ __nv_bfloat16 g_wtl[WTOT];

// ---------------- helpers -----------------------------------------------------
__device__ __forceinline__ uint32_t smem_u32(const void* p) {
    uint32_t a;
    asm("{ .reg .u64 t; cvta.to.shared.u64 t, %1; cvt.u32.u64 %0, t; }" : "=r"(a) : "l"(p));
    return a;
}

__device__ __forceinline__ void ldsm4(uint32_t (&r)[4], uint32_t addr) {
    asm volatile("ldmatrix.sync.aligned.m8n8.x4.shared.b16 {%0,%1,%2,%3}, [%4];"
                 : "=r"(r[0]), "=r"(r[1]), "=r"(r[2]), "=r"(r[3]) : "r"(addr));
}

__device__ __forceinline__ void mma16816(float (&c)[4], const uint32_t (&a)[4],
                                         uint32_t b0, uint32_t b1) {
    asm volatile(
        "mma.sync.aligned.m16n8k16.row.col.f32.bf16.bf16.f32 "
        "{%0,%1,%2,%3},{%4,%5,%6,%7},{%8,%9},{%0,%1,%2,%3};"
        : "+f"(c[0]), "+f"(c[1]), "+f"(c[2]), "+f"(c[3])
        : "r"(a[0]), "r"(a[1]), "r"(a[2]), "r"(a[3]), "r"(b0), "r"(b1));
}

__device__ __forceinline__ void split2(float a, float b, uint32_t& hv, uint32_t& lv) {
    __nv_bfloat16 ha = __float2bfloat16(a), hb = __float2bfloat16(b);
    float la = a - __bfloat162float(ha), lb = b - __bfloat162float(hb);
    __nv_bfloat162 hp = __halves2bfloat162(ha, hb);
    __nv_bfloat162 lp = __floats2bfloat162_rn(la, lb);
    hv = *reinterpret_cast<uint32_t*>(&hp);
    lv = *reinterpret_cast<uint32_t*>(&lp);
}

// ---------------- smem layout for fused MLP kernel -----------------------------
// A tile: 64 rows x (<=128) cols, pitch 136 bf16. B tile: 128 rows x 128, pitch 136.
#define PITCH 136
#define OFF_A_HI 0u
#define OFF_A_LO 17408u
#define OFF_B_HI 34816u
#define OFF_B_LO 69632u
#define SMEM_FUSED 104448

// ---- GEMM stage: acc[2][4][4] = (A 64xKs split) @ (B^T 128xKs split), 3 combos --
template<int Ks>
__device__ __forceinline__ void gemm_acc(uint32_t sb, float (&acc)[2][4][4],
                                         int lane, int warp_m, int warp_n) {
#pragma unroll
    for (int i = 0; i < 2; i++)
#pragma unroll
        for (int j = 0; j < 4; j++)
#pragma unroll
            for (int k = 0; k < 4; k++) acc[i][j][k] = 0.f;

    int a_r = lane & 15;
    int a_c = (lane & 16) ? 8 : 0;
    int b_r = (lane & 7) + ((lane & 16) ? 8 : 0);
    int b_c = (lane & 8) ? 8 : 0;

#pragma unroll
    for (int kk = 0; kk < Ks / 16; kk++) {
        uint32_t ah[2][4], al[2][4], bh[2][4], bl[2][4];
#pragma unroll
        for (int mt = 0; mt < 2; mt++) {
            uint32_t off = (uint32_t)(((warp_m * 32 + mt * 16 + a_r) * PITCH + kk * 16 + a_c) * 2);
            ldsm4(ah[mt], sb + OFF_A_HI + off);
            ldsm4(al[mt], sb + OFF_A_LO + off);
        }
#pragma unroll
        for (int p = 0; p < 2; p++) {
            uint32_t off = (uint32_t)(((warp_n * 32 + p * 16 + b_r) * PITCH + kk * 16 + b_c) * 2);
            ldsm4(bh[p], sb + OFF_B_HI + off);
            ldsm4(bl[p], sb + OFF_B_LO + off);
        }
#pragma unroll
        for (int mt = 0; mt < 2; mt++)
#pragma unroll
            for (int nt = 0; nt < 4; nt++) {
                int p = nt >> 1, q = (nt & 1) * 2;
                mma16816(acc[mt][nt], ah[mt], bh[p][q], bh[p][q + 1]);
                mma16816(acc[mt][nt], ah[mt], bl[p][q], bl[p][q + 1]);
                mma16816(acc[mt][nt], al[mt], bh[p][q], bh[p][q + 1]);
            }
    }
}

// ---- relu(acc+bias) -> split pair into A smem tile ----------------------------
__device__ __forceinline__ void stage_to_smem(char* smem, float (&acc)[2][4][4],
                                              const float* __restrict__ bias,
                                              int lane, int warp_m, int warp_n) {
    int qrow = lane >> 2, qcol = (lane & 3) * 2;
#pragma unroll
    for (int mt = 0; mt < 2; mt++) {
        int r0 = warp_m * 32 + mt * 16 + qrow;
#pragma unroll
        for (int nt = 0; nt < 4; nt++) {
            int col = warp_n * 32 + nt * 8 + qcol;
            float bs0 = __ldg(bias + col), bs1 = __ldg(bias + col + 1);
            float o0 = fmaxf(acc[mt][nt][0] + bs0, 0.f);
            float o1 = fmaxf(acc[mt][nt][1] + bs1, 0.f);
            float o2 = fmaxf(acc[mt][nt][2] + bs0, 0.f);
            float o3 = fmaxf(acc[mt][nt][3] + bs1, 0.f);
            uint32_t h0, l0, h1, l1;
            split2(o0, o1, h0, l0);
            split2(o2, o3, h1, l1);
            *reinterpret_cast<uint32_t*>(smem + OFF_A_HI + ((size_t)r0 * PITCH + col) * 2) = h0;
            *reinterpret_cast<uint32_t*>(smem + OFF_A_LO + ((size_t)r0 * PITCH + col) * 2) = l0;
            *reinterpret_cast<uint32_t*>(smem + OFF_A_HI + ((size_t)(r0 + 8) * PITCH + col) * 2) = h1;
            *reinterpret_cast<uint32_t*>(smem + OFF_A_LO + ((size_t)(r0 + 8) * PITCH + col) * 2) = l1;
        }
    }
}

// ---- load weight tile (128 x Kw) into B smem -----------------------------------
template<int Kw>
__device__ __forceinline__ void load_w(char* smem, const __nv_bfloat16* __restrict__ wh,
                                       const __nv_bfloat16* __restrict__ wl, int tid) {
    constexpr int CH = Kw / 8;
    constexpr int ITER = 128 * CH / 256;
#pragma unroll
    for (int it = 0; it < ITER; it++) {
        int l = tid + it * 256;
        int row = l / CH, col = (l % CH) * 8;
        *reinterpret_cast<uint4*>(smem + OFF_B_HI + ((size_t)row * PITCH + col) * 2) =
            *reinterpret_cast<const uint4*>(wh + (size_t)row * Kw + col);
        *reinterpret_cast<uint4*>(smem + OFF_B_LO + ((size_t)row * PITCH + col) * 2) =
            *reinterpret_cast<const uint4*>(wl + (size_t)row * Kw + col);
    }
}

struct FusedW {
    const __nv_bfloat16* wh[3];
    const __nv_bfloat16* wl[3];
    const float* b[3];
};

// ---------------- fused MLP: NST chained GEMMs, tile = 64 rows -------------------
// IN: 0 = A fp32;  1 = A + A2 fp32 (fused GIN self-add).  Output fp32 (after ReLU).
template<int K0, int NST, int IN>
__global__ __launch_bounds__(256, 2)
void fused_mlp(const float* __restrict__ A, const float* __restrict__ A2,
               FusedW fw, float* __restrict__ C, int M) {
    extern __shared__ char smem[];
    uint32_t sb = smem_u32(smem);
    int tid = threadIdx.x, lane = tid & 31, wid = tid >> 5;
    int warp_m = wid & 1, warp_n = wid >> 1;
    int m0 = blockIdx.x * 64;

    // ---- load + split A (64 x K0) ----
    {
        constexpr int CH = K0 / 4;
        constexpr int ITER = 64 * CH / 256;
#pragma unroll
        for (int it = 0; it < ITER; it++) {
            int l = tid + it * 256;
            int row = l / CH, col = (l % CH) * 4;
            float4 v = make_float4(0.f, 0.f, 0.f, 0.f);
            int m = m0 + row;
            if (m < M) {
                v = *reinterpret_cast<const float4*>(A + (size_t)m * K0 + col);
                if (IN == 1) {
                    float4 w = *reinterpret_cast<const float4*>(A2 + (size_t)m * K0 + col);
                    v.x += w.x; v.y += w.y; v.z += w.z; v.w += w.w;
                }
            }
            uint32_t h0, l0, h1, l1;
            split2(v.x, v.y, h0, l0);
            split2(v.z, v.w, h1, l1);
            *reinterpret_cast<uint2*>(smem + OFF_A_HI + ((size_t)row * PITCH + col) * 2) = make_uint2(h0, h1);
            *reinterpret_cast<uint2*>(smem + OFF_A_LO + ((size_t)row * PITCH + col) * 2) = make_uint2(l0, l1);
        }
    }
    load_w<K0>(smem, fw.wh[0], fw.wl[0], tid);
    __syncthreads();

    float acc[2][4][4];
    gemm_acc<K0>(sb, acc, lane, warp_m, warp_n);

#pragma unroll
    for (int s = 1; s < NST; s++) {
        __syncthreads();                         // everyone done reading sA/sB
        stage_to_smem(smem, acc, fw.b[s - 1], lane, warp_m, warp_n);
        load_w<128>(smem, fw.wh[s], fw.wl[s], tid);
        __syncthreads();
        gemm_acc<128>(sb, acc, lane, warp_m, warp_n);
    }

    // ---- final epilogue: relu(acc+bias) -> fp32 global ----
    const float* bias = fw.b[NST - 1];
    int qrow = lane >> 2, qcol = (lane & 3) * 2;
#pragma unroll
    for (int mt = 0; mt < 2; mt++) {
        int r0 = m0 + warp_m * 32 + mt * 16 + qrow;
        int r1 = r0 + 8;
#pragma unroll
        for (int nt = 0; nt < 4; nt++) {
            int col = warp_n * 32 + nt * 8 + qcol;
            float bs0 = __ldg(bias + col), bs1 = __ldg(bias + col + 1);
            float o0 = fmaxf(acc[mt][nt][0] + bs0, 0.f);
            float o1 = fmaxf(acc[mt][nt][1] + bs1, 0.f);
            float o2 = fmaxf(acc[mt][nt][2] + bs0, 0.f);
            float o3 = fmaxf(acc[mt][nt][3] + bs1, 0.f);
            if (r0 < M) *reinterpret_cast<float2*>(C + (size_t)r0 * 128 + col) = make_float2(o0, o1);
            if (r1 < M) *reinterpret_cast<float2*>(C + (size_t)r1 * 128 + col) = make_float2(o2, o3);
        }
    }
}

// ---------------- weight prep (11 slots, one launch) ---------------------------
struct WP { const float* p[11]; };

__global__ void prep_all(WP wp, __nv_bfloat16* __restrict__ hi, __nv_bfloat16* __restrict__ lo) {
    int slot = blockIdx.x >> 7;
    int n = blockIdx.x & 127;
    int K = (slot == 0) ? FIN : Hh;
    size_t off = (slot == 0) ? 0 : (size_t)4096 + (size_t)(slot - 1) * 16384;
    const float* W = wp.p[slot];
    for (int k = threadIdx.x; k < K; k += blockDim.x) {
        float v = W[k * Hh + n];
        __nv_bfloat16 h = __float2bfloat16(v);
        hi[off + (size_t)n * K + k] = h;
        lo[off + (size_t)n * K + k] = __float2bfloat16(v - __bfloat162float(h));
    }
}

// ---------------- graph ops -----------------------------------------------------
__global__ void zero_k(float* p, int n) {
    int i = blockIdx.x * blockDim.x + threadIdx.x;
    if (i < n) p[i] = 0.f;
}

template<int K>
__global__ void scatter_k(float* __restrict__ agg, const float* __restrict__ h,
                          const int* __restrict__ ei) {
    const int C = K / 4;
    int idx = blockIdx.x * blockDim.x + threadIdx.x;
    if (idx >= Ee * C) return;
    int e = idx / C;
    int c = idx - e * C;
    int s = ei[e];
    int d = ei[Ee + e];
    float4 v = reinterpret_cast<const float4*>(h)[s * C + c];
    float* dst = agg + (size_t)d * K + c * 4;
    atomicAdd(dst + 0, v.x);
    atomicAdd(dst + 1, v.y);
    atomicAdd(dst + 2, v.z);
    atomicAdd(dst + 3, v.w);
}

// run-length pooled mean (batch is sorted)
#define PR 16
__global__ void pool_k(const float* __restrict__ h, const int* __restrict__ batch,
                       float* __restrict__ pool) {
    int gw = (blockIdx.x * blockDim.x + threadIdx.x) >> 5;
    int lane = threadIdx.x & 31;
    const int NB = (Nn + PR - 1) / PR;
    if (gw >= NB * 4) return;
    int nb = gw >> 2, fc = gw & 3;
    int f = fc * 32 + lane;
    int n0 = nb * PR;
    int n1 = n0 + PR < Nn ? n0 + PR : Nn;
    float acc = 0.f;
    int cur = batch[n0];
    for (int n = n0; n < n1; n++) {
        int g = batch[n];
        if (g != cur) {
            atomicAdd(&pool[(size_t)cur * Hh + f], acc);
            acc = 0.f;
            cur = g;
        }
        acc += h[(size_t)n * Hh + f];
    }
    atomicAdd(&pool[(size_t)cur * Hh + f], acc);
}

__global__ void cnt_k(const int* __restrict__ batch, float* __restrict__ cnt) {
    int t = blockIdx.x * blockDim.x + threadIdx.x;
    const int R = 32;
    int n0 = t * R;
    if (n0 >= Nn) return;
    int n1 = n0 + R < Nn ? n0 + R : Nn;
    float acc = 0.f;
    int cur = batch[n0];
    for (int n = n0; n < n1; n++) {
        int g = batch[n];
        if (g != cur) { atomicAdd(&cnt[cur], acc); acc = 0.f; cur = g; }
        acc += 1.f;
    }
    atomicAdd(&cnt[cur], acc);
}

__global__ void div_k(float* __restrict__ pool, const float* __restrict__ cnt) {
    int idx = blockIdx.x * blockDim.x + threadIdx.x;
    if (idx >= Gg * Hh) return;
    pool[idx] *= 1.f / fmaxf(cnt[idx >> 7], 1.f);
}

__global__ void out_k(const float* __restrict__ g2, const float* __restrict__ ow,
                      const float* __restrict__ ob, float* __restrict__ out) {
    int g = blockIdx.x * blockDim.x + threadIdx.x;
    if (g >= Gg) return;
    float s0 = ob[0], s1 = ob[1];
#pragma unroll 4
    for (int k = 0; k < Hh; k++) {
        float v = g2[g * Hh + k];
        s0 += v * ow[k * 2 + 0];
        s1 += v * ow[k * 2 + 1];
    }
    out[g * 2 + 0] = s0;
    out[g * 2 + 1] = s1;
}

// ---------------- launch ----------------------------------------------------------
extern "C" void kernel_launch(void* const* d_in, const int* in_sizes, int n_in,
                              void* d_out, int out_size) {
    const float* x     = (const float*)d_in[0];
    const int*   ei    = (const int*)  d_in[1];
    const int*   batch = (const int*)  d_in[2];
    const float* b1[3], *b2[3], *b3[3];
    WP wp;
    for (int L = 0; L < 3; L++) {
        wp.p[3 * L + 0] = (const float*)d_in[3 + 6 * L + 0];
        b1[L]           = (const float*)d_in[3 + 6 * L + 1];
        wp.p[3 * L + 1] = (const float*)d_in[3 + 6 * L + 2];
        b2[L]           = (const float*)d_in[3 + 6 * L + 3];
        wp.p[3 * L + 2] = (const float*)d_in[3 + 6 * L + 4];
        b3[L]           = (const float*)d_in[3 + 6 * L + 5];
    }
    wp.p[9]  = (const float*)d_in[21];
    const float* fc0b = (const float*)d_in[22];
    wp.p[10] = (const float*)d_in[23];
    const float* fc1b = (const float*)d_in[24];
    const float* outw = (const float*)d_in[25];
    const float* outb = (const float*)d_in[26];

    float *agg, *h, *pool, *cnt, *hd2;
    __nv_bfloat16 *wth, *wtl;
    cudaGetSymbolAddress((void**)&agg,  g_agg);
    cudaGetSymbolAddress((void**)&h,    g_h);
    cudaGetSymbolAddress((void**)&pool, g_pool);
    cudaGetSymbolAddress((void**)&cnt,  g_cnt);
    cudaGetSymbolAddress((void**)&hd2,  g_hd2);
    cudaGetSymbolAddress((void**)&wth,  g_wth);
    cudaGetSymbolAddress((void**)&wtl,  g_wtl);

    auto woff = [](int s) -> size_t { return s == 0 ? 0 : (size_t)4096 + (size_t)(s - 1) * 16384; };

    cudaFuncSetAttribute(fused_mlp<FIN, 3, 1>, cudaFuncAttributeMaxDynamicSharedMemorySize, SMEM_FUSED);
    cudaFuncSetAttribute(fused_mlp<Hh, 3, 1>,  cudaFuncAttributeMaxDynamicSharedMemorySize, SMEM_FUSED);
    cudaFuncSetAttribute(fused_mlp<Hh, 2, 0>,  cudaFuncAttributeMaxDynamicSharedMemorySize, SMEM_FUSED);

    const int TB = 256;
    int ggrid = (Nn + 63) / 64;   // 2344
    int hgrid = (Gg + 63) / 64;   // 32

    prep_all<<<11 * 128, 128>>>(wp, wth, wtl);

    for (int L = 0; L < 3; L++) {
        FusedW fw;
        for (int s = 0; s < 3; s++) {
            fw.wh[s] = wth + woff(3 * L + s);
            fw.wl[s] = wtl + woff(3 * L + s);
        }
        fw.b[0] = b1[L]; fw.b[1] = b2[L]; fw.b[2] = b3[L];

        if (L == 0) {
            zero_k<<<(Nn * FIN + TB - 1) / TB, TB>>>(agg, Nn * FIN);
            scatter_k<FIN><<<(Ee * (FIN / 4) + TB - 1) / TB, TB>>>(agg, x, ei);
            fused_mlp<FIN, 3, 1><<<ggrid, 256, SMEM_FUSED>>>(agg, x, fw, h, Nn);
        } else {
            zero_k<<<(Nn * Hh + TB - 1) / TB, TB>>>(agg, Nn * Hh);
            scatter_k<Hh><<<(Ee * (Hh / 4) + TB - 1) / TB, TB>>>(agg, h, ei);
            fused_mlp<Hh, 3, 1><<<ggrid, 256, SMEM_FUSED>>>(agg, h, fw, h, Nn);
        }
    }

    // ---- global mean pool ----
    zero_k<<<(Gg * Hh + TB - 1) / TB, TB>>>(pool, Gg * Hh);
    zero_k<<<(Gg + TB - 1) / TB, TB>>>(cnt, Gg);
    {
        int warps = ((Nn + PR - 1) / PR) * 4;
        pool_k<<<(warps * 32 + TB - 1) / TB, TB>>>(h, batch, pool);
    }
    cnt_k<<<((Nn + 31) / 32 + TB - 1) / TB, TB>>>(batch, cnt);
    div_k<<<(Gg * Hh + TB - 1) / TB, TB>>>(pool, cnt);

    // ---- classifier head (fc0 + fc1 fused) ----
    {
        FusedW fw;
        fw.wh[0] = wth + woff(9);  fw.wl[0] = wtl + woff(9);
        fw.wh[1] = wth + woff(10); fw.wl[1] = wtl + woff(10);
        fw.wh[2] = nullptr;        fw.wl[2] = nullptr;
        fw.b[0] = fc0b; fw.b[1] = fc1b; fw.b[2] = nullptr;
        fused_mlp<Hh, 2, 0><<<hgrid, 256, SMEM_FUSED>>>(pool, nullptr, fw, hd2, Gg);
    }
    out_k<<<(Gg + 127) / 128, 128>>>(hd2, outw, outb, (float*)d_out);
}

// round 5
// speedup vs baseline: 2.2615x; 1.3517x over previous
#include <cuda_runtime.h>
#include <cuda_bf16.h>
#include <cstdint>

#define Nn  150000
#define Ee  600000
#define FIN 32
#define Hh  128
#define Gg  2048

// ---------------- scratch (device globals) ----------------------------------
__device__ float g_agg[Nn * Hh];
__device__ float g_h  [Nn * Hh];
__device__ float g_pool[Gg * Hh];
__device__ float g_cnt [Gg];
__device__ float g_hd2 [Gg * Hh];
#define WTOT (4096 + 10 * 16384)
__device__ __nv_bfloat16 g_wth[WTOT];
__device__ __nv_bfloat16 g_wtl[WTOT];

// ---------------- helpers -----------------------------------------------------
__device__ __forceinline__ uint32_t smem_u32(const void* p) {
    uint32_t a;
    asm("{ .reg .u64 t; cvta.to.shared.u64 t, %1; cvt.u32.u64 %0, t; }" : "=r"(a) : "l"(p));
    return a;
}

__device__ __forceinline__ void ldsm4(uint32_t (&r)[4], uint32_t addr) {
    asm volatile("ldmatrix.sync.aligned.m8n8.x4.shared.b16 {%0,%1,%2,%3}, [%4];"
                 : "=r"(r[0]), "=r"(r[1]), "=r"(r[2]), "=r"(r[3]) : "r"(addr));
}

__device__ __forceinline__ void mma16816(float (&c)[4], const uint32_t (&a)[4],
                                         uint32_t b0, uint32_t b1) {
    asm volatile(
        "mma.sync.aligned.m16n8k16.row.col.f32.bf16.bf16.f32 "
        "{%0,%1,%2,%3},{%4,%5,%6,%7},{%8,%9},{%0,%1,%2,%3};"
        : "+f"(c[0]), "+f"(c[1]), "+f"(c[2]), "+f"(c[3])
        : "r"(a[0]), "r"(a[1]), "r"(a[2]), "r"(a[3]), "r"(b0), "r"(b1));
}

__device__ __forceinline__ void split2(float a, float b, uint32_t& hv, uint32_t& lv) {
    __nv_bfloat16 ha = __float2bfloat16(a), hb = __float2bfloat16(b);
    float la = a - __bfloat162float(ha), lb = b - __bfloat162float(hb);
    __nv_bfloat162 hp = __halves2bfloat162(ha, hb);
    __nv_bfloat162 lp = __floats2bfloat162_rn(la, lb);
    hv = *reinterpret_cast<uint32_t*>(&hp);
    lv = *reinterpret_cast<uint32_t*>(&lp);
}

// vectorized fp32 reduction (sm_90+, base-target feature)
__device__ __forceinline__ void red4(float* p, float4 v) {
    asm volatile("red.global.add.v4.f32 [%0], {%1, %2, %3, %4};"
                 :: "l"(p), "f"(v.x), "f"(v.y), "f"(v.z), "f"(v.w) : "memory");
}

// ---------------- smem layout for fused MLP kernel -----------------------------
#define PITCH 136
#define OFF_A_HI 0u
#define OFF_A_LO 17408u
#define OFF_B_HI 34816u
#define OFF_B_LO 69632u
#define SMEM_FUSED 104448

template<int Ks>
__device__ __forceinline__ void gemm_acc(uint32_t sb, float (&acc)[2][4][4],
                                         int lane, int warp_m, int warp_n) {
#pragma unroll
    for (int i = 0; i < 2; i++)
#pragma unroll
        for (int j = 0; j < 4; j++)
#pragma unroll
            for (int k = 0; k < 4; k++) acc[i][j][k] = 0.f;

    int a_r = lane & 15;
    int a_c = (lane & 16) ? 8 : 0;
    int b_r = (lane & 7) + ((lane & 16) ? 8 : 0);
    int b_c = (lane & 8) ? 8 : 0;

#pragma unroll
    for (int kk = 0; kk < Ks / 16; kk++) {
        uint32_t ah[2][4], al[2][4], bh[2][4], bl[2][4];
#pragma unroll
        for (int mt = 0; mt < 2; mt++) {
            uint32_t off = (uint32_t)(((warp_m * 32 + mt * 16 + a_r) * PITCH + kk * 16 + a_c) * 2);
            ldsm4(ah[mt], sb + OFF_A_HI + off);
            ldsm4(al[mt], sb + OFF_A_LO + off);
        }
#pragma unroll
        for (int p = 0; p < 2; p++) {
            uint32_t off = (uint32_t)(((warp_n * 32 + p * 16 + b_r) * PITCH + kk * 16 + b_c) * 2);
            ldsm4(bh[p], sb + OFF_B_HI + off);
            ldsm4(bl[p], sb + OFF_B_LO + off);
        }
#pragma unroll
        for (int mt = 0; mt < 2; mt++)
#pragma unroll
            for (int nt = 0; nt < 4; nt++) {
                int p = nt >> 1, q = (nt & 1) * 2;
                mma16816(acc[mt][nt], ah[mt], bh[p][q], bh[p][q + 1]);
                mma16816(acc[mt][nt], ah[mt], bl[p][q], bl[p][q + 1]);
                mma16816(acc[mt][nt], al[mt], bh[p][q], bh[p][q + 1]);
            }
    }
}

__device__ __forceinline__ void stage_to_smem(char* smem, float (&acc)[2][4][4],
                                              const float* __restrict__ bias,
                                              int lane, int warp_m, int warp_n) {
    int qrow = lane >> 2, qcol = (lane & 3) * 2;
#pragma unroll
    for (int mt = 0; mt < 2; mt++) {
        int r0 = warp_m * 32 + mt * 16 + qrow;
#pragma unroll
        for (int nt = 0; nt < 4; nt++) {
            int col = warp_n * 32 + nt * 8 + qcol;
            float bs0 = __ldg(bias + col), bs1 = __ldg(bias + col + 1);
            float o0 = fmaxf(acc[mt][nt][0] + bs0, 0.f);
            float o1 = fmaxf(acc[mt][nt][1] + bs1, 0.f);
            float o2 = fmaxf(acc[mt][nt][2] + bs0, 0.f);
            float o3 = fmaxf(acc[mt][nt][3] + bs1, 0.f);
            uint32_t h0, l0, h1, l1;
            split2(o0, o1, h0, l0);
            split2(o2, o3, h1, l1);
            *reinterpret_cast<uint32_t*>(smem + OFF_A_HI + ((size_t)r0 * PITCH + col) * 2) = h0;
            *reinterpret_cast<uint32_t*>(smem + OFF_A_LO + ((size_t)r0 * PITCH + col) * 2) = l0;
            *reinterpret_cast<uint32_t*>(smem + OFF_A_HI + ((size_t)(r0 + 8) * PITCH + col) * 2) = h1;
            *reinterpret_cast<uint32_t*>(smem + OFF_A_LO + ((size_t)(r0 + 8) * PITCH + col) * 2) = l1;
        }
    }
}

template<int Kw>
__device__ __forceinline__ void load_w(char* smem, const __nv_bfloat16* __restrict__ wh,
                                       const __nv_bfloat16* __restrict__ wl, int tid) {
    constexpr int CH = Kw / 8;
    constexpr int ITER = 128 * CH / 256;
#pragma unroll
    for (int it = 0; it < ITER; it++) {
        int l = tid + it * 256;
        int row = l / CH, col = (l % CH) * 8;
        *reinterpret_cast<uint4*>(smem + OFF_B_HI + ((size_t)row * PITCH + col) * 2) =
            *reinterpret_cast<const uint4*>(wh + (size_t)row * Kw + col);
        *reinterpret_cast<uint4*>(smem + OFF_B_LO + ((size_t)row * PITCH + col) * 2) =
            *reinterpret_cast<const uint4*>(wl + (size_t)row * Kw + col);
    }
}

struct FusedW {
    const __nv_bfloat16* wh[3];
    const __nv_bfloat16* wl[3];
    const float* b[3];
};

template<int K0, int NST, int IN>
__global__ __launch_bounds__(256, 2)
void fused_mlp(const float* __restrict__ A, const float* __restrict__ A2,
               FusedW fw, float* __restrict__ C, int M) {
    extern __shared__ char smem[];
    uint32_t sb = smem_u32(smem);
    int tid = threadIdx.x, lane = tid & 31, wid = tid >> 5;
    int warp_m = wid & 1, warp_n = wid >> 1;
    int m0 = blockIdx.x * 64;

    {
        constexpr int CH = K0 / 4;
        constexpr int ITER = 64 * CH / 256;
#pragma unroll
        for (int it = 0; it < ITER; it++) {
            int l = tid + it * 256;
            int row = l / CH, col = (l % CH) * 4;
            float4 v = make_float4(0.f, 0.f, 0.f, 0.f);
            int m = m0 + row;
            if (m < M) {
                v = *reinterpret_cast<const float4*>(A + (size_t)m * K0 + col);
                if (IN == 1) {
                    float4 w = *reinterpret_cast<const float4*>(A2 + (size_t)m * K0 + col);
                    v.x += w.x; v.y += w.y; v.z += w.z; v.w += w.w;
                }
            }
            uint32_t h0, l0, h1, l1;
            split2(v.x, v.y, h0, l0);
            split2(v.z, v.w, h1, l1);
            *reinterpret_cast<uint2*>(smem + OFF_A_HI + ((size_t)row * PITCH + col) * 2) = make_uint2(h0, h1);
            *reinterpret_cast<uint2*>(smem + OFF_A_LO + ((size_t)row * PITCH + col) * 2) = make_uint2(l0, l1);
        }
    }
    load_w<K0>(smem, fw.wh[0], fw.wl[0], tid);
    __syncthreads();

    float acc[2][4][4];
    gemm_acc<K0>(sb, acc, lane, warp_m, warp_n);

#pragma unroll
    for (int s = 1; s < NST; s++) {
        __syncthreads();
        stage_to_smem(smem, acc, fw.b[s - 1], lane, warp_m, warp_n);
        load_w<128>(smem, fw.wh[s], fw.wl[s], tid);
        __syncthreads();
        gemm_acc<128>(sb, acc, lane, warp_m, warp_n);
    }

    const float* bias = fw.b[NST - 1];
    int qrow = lane >> 2, qcol = (lane & 3) * 2;
#pragma unroll
    for (int mt = 0; mt < 2; mt++) {
        int r0 = m0 + warp_m * 32 + mt * 16 + qrow;
        int r1 = r0 + 8;
#pragma unroll
        for (int nt = 0; nt < 4; nt++) {
            int col = warp_n * 32 + nt * 8 + qcol;
            float bs0 = __ldg(bias + col), bs1 = __ldg(bias + col + 1);
            float o0 = fmaxf(acc[mt][nt][0] + bs0, 0.f);
            float o1 = fmaxf(acc[mt][nt][1] + bs1, 0.f);
            float o2 = fmaxf(acc[mt][nt][2] + bs0, 0.f);
            float o3 = fmaxf(acc[mt][nt][3] + bs1, 0.f);
            if (r0 < M) *reinterpret_cast<float2*>(C + (size_t)r0 * 128 + col) = make_float2(o0, o1);
            if (r1 < M) *reinterpret_cast<float2*>(C + (size_t)r1 * 128 + col) = make_float2(o2, o3);
        }
    }
}

// ---------------- weight prep (11 slots, one launch) ---------------------------
struct WP { const float* p[11]; };

__global__ void prep_all(WP wp, __nv_bfloat16* __restrict__ hi, __nv_bfloat16* __restrict__ lo) {
    int slot = blockIdx.x >> 7;
    int n = blockIdx.x & 127;
    int K = (slot == 0) ? FIN : Hh;
    size_t off = (slot == 0) ? 0 : (size_t)4096 + (size_t)(slot - 1) * 16384;
    const float* W = wp.p[slot];
    for (int k = threadIdx.x; k < K; k += blockDim.x) {
        float v = W[k * Hh + n];
        __nv_bfloat16 h = __float2bfloat16(v);
        hi[off + (size_t)n * K + k] = h;
        lo[off + (size_t)n * K + k] = __float2bfloat16(v - __bfloat162float(h));
    }
}

// ---------------- graph ops -----------------------------------------------------
__global__ void zero_k(float4* p, int n4) {
    int i = blockIdx.x * blockDim.x + threadIdx.x;
    if (i < n4) p[i] = make_float4(0.f, 0.f, 0.f, 0.f);
}

// edge scatter: one red.global.add.v4.f32 per thread-chunk
template<int K>
__global__ void scatter_k(float* __restrict__ agg, const float* __restrict__ h,
                          const int* __restrict__ ei) {
    const int C = K / 4;
    int idx = blockIdx.x * blockDim.x + threadIdx.x;
    if (idx >= Ee * C) return;
    int e = idx / C;
    int c = idx - e * C;
    int s = ei[e];
    int d = ei[Ee + e];
    float4 v = reinterpret_cast<const float4*>(h)[(size_t)s * C + c];
    red4(agg + (size_t)d * K + c * 4, v);
}

// pooled mean: one warp covers all 128 features of a run of PR sorted nodes
#define PR 16
__global__ void pool_k(const float* __restrict__ h, const int* __restrict__ batch,
                       float* __restrict__ pool) {
    int gw = (blockIdx.x * blockDim.x + threadIdx.x) >> 5;
    int lane = threadIdx.x & 31;
    const int NB = (Nn + PR - 1) / PR;
    if (gw >= NB) return;
    int n0 = gw * PR;
    int n1 = n0 + PR < Nn ? n0 + PR : Nn;
    float4 acc = make_float4(0.f, 0.f, 0.f, 0.f);
    int cur = batch[n0];
    for (int n = n0; n < n1; n++) {
        int g = batch[n];
        if (g != cur) {
            red4(&pool[(size_t)cur * Hh + lane * 4], acc);
            acc = make_float4(0.f, 0.f, 0.f, 0.f);
            cur = g;
        }
        float4 v = *reinterpret_cast<const float4*>(h + (size_t)n * Hh + lane * 4);
        acc.x += v.x; acc.y += v.y; acc.z += v.z; acc.w += v.w;
    }
    red4(&pool[(size_t)cur * Hh + lane * 4], acc);
}

__global__ void cnt_k(const int* __restrict__ batch, float* __restrict__ cnt) {
    int t = blockIdx.x * blockDim.x + threadIdx.x;
    const int R = 32;
    int n0 = t * R;
    if (n0 >= Nn) return;
    int n1 = n0 + R < Nn ? n0 + R : Nn;
    float acc = 0.f;
    int cur = batch[n0];
    for (int n = n0; n < n1; n++) {
        int g = batch[n];
        if (g != cur) { atomicAdd(&cnt[cur], acc); acc = 0.f; cur = g; }
        acc += 1.f;
    }
    atomicAdd(&cnt[cur], acc);
}

__global__ void div_k(float* __restrict__ pool, const float* __restrict__ cnt) {
    int idx = blockIdx.x * blockDim.x + threadIdx.x;
    if (idx >= Gg * Hh) return;
    pool[idx] *= 1.f / fmaxf(cnt[idx >> 7], 1.f);
}

__global__ void out_k(const float* __restrict__ g2, const float* __restrict__ ow,
                      const float* __restrict__ ob, float* __restrict__ out) {
    int g = blockIdx.x * blockDim.x + threadIdx.x;
    if (g >= Gg) return;
    float s0 = ob[0], s1 = ob[1];
#pragma unroll 4
    for (int k = 0; k < Hh; k++) {
        float v = g2[g * Hh + k];
        s0 += v * ow[k * 2 + 0];
        s1 += v * ow[k * 2 + 1];
    }
    out[g * 2 + 0] = s0;
    out[g * 2 + 1] = s1;
}

// ---------------- launch ----------------------------------------------------------
extern "C" void kernel_launch(void* const* d_in, const int* in_sizes, int n_in,
                              void* d_out, int out_size) {
    const float* x     = (const float*)d_in[0];
    const int*   ei    = (const int*)  d_in[1];
    const int*   batch = (const int*)  d_in[2];
    const float* b1[3], *b2[3], *b3[3];
    WP wp;
    for (int L = 0; L < 3; L++) {
        wp.p[3 * L + 0] = (const float*)d_in[3 + 6 * L + 0];
        b1[L]           = (const float*)d_in[3 + 6 * L + 1];
        wp.p[3 * L + 1] = (const float*)d_in[3 + 6 * L + 2];
        b2[L]           = (const float*)d_in[3 + 6 * L + 3];
        wp.p[3 * L + 2] = (const float*)d_in[3 + 6 * L + 4];
        b3[L]           = (const float*)d_in[3 + 6 * L + 5];
    }
    wp.p[9]  = (const float*)d_in[21];
    const float* fc0b = (const float*)d_in[22];
    wp.p[10] = (const float*)d_in[23];
    const float* fc1b = (const float*)d_in[24];
    const float* outw = (const float*)d_in[25];
    const float* outb = (const float*)d_in[26];

    float *agg, *h, *pool, *cnt, *hd2;
    __nv_bfloat16 *wth, *wtl;
    cudaGetSymbolAddress((void**)&agg,  g_agg);
    cudaGetSymbolAddress((void**)&h,    g_h);
    cudaGetSymbolAddress((void**)&pool, g_pool);
    cudaGetSymbolAddress((void**)&cnt,  g_cnt);
    cudaGetSymbolAddress((void**)&hd2,  g_hd2);
    cudaGetSymbolAddress((void**)&wth,  g_wth);
    cudaGetSymbolAddress((void**)&wtl,  g_wtl);

    auto woff = [](int s) -> size_t { return s == 0 ? 0 : (size_t)4096 + (size_t)(s - 1) * 16384; };

    cudaFuncSetAttribute(fused_mlp<FIN, 3, 1>, cudaFuncAttributeMaxDynamicSharedMemorySize, SMEM_FUSED);
    cudaFuncSetAttribute(fused_mlp<Hh, 3, 1>,  cudaFuncAttributeMaxDynamicSharedMemorySize, SMEM_FUSED);
    cudaFuncSetAttribute(fused_mlp<Hh, 2, 0>,  cudaFuncAttributeMaxDynamicSharedMemorySize, SMEM_FUSED);

    const int TB = 256;
    int ggrid = (Nn + 63) / 64;   // 2344
    int hgrid = (Gg + 63) / 64;   // 32

    prep_all<<<11 * 128, 128>>>(wp, wth, wtl);

    for (int L = 0; L < 3; L++) {
        FusedW fw;
        for (int s = 0; s < 3; s++) {
            fw.wh[s] = wth + woff(3 * L + s);
            fw.wl[s] = wtl + woff(3 * L + s);
        }
        fw.b[0] = b1[L]; fw.b[1] = b2[L]; fw.b[2] = b3[L];

        if (L == 0) {
            zero_k<<<(Nn * FIN / 4 + TB - 1) / TB, TB>>>((float4*)agg, Nn * FIN / 4);
            scatter_k<FIN><<<(Ee * (FIN / 4) + TB - 1) / TB, TB>>>(agg, x, ei);
            fused_mlp<FIN, 3, 1><<<ggrid, 256, SMEM_FUSED>>>(agg, x, fw, h, Nn);
        } else {
            zero_k<<<(Nn * Hh / 4 + TB - 1) / TB, TB>>>((float4*)agg, Nn * Hh / 4);
            scatter_k<Hh><<<(Ee * (Hh / 4) + TB - 1) / TB, TB>>>(agg, h, ei);
            fused_mlp<Hh, 3, 1><<<ggrid, 256, SMEM_FUSED>>>(agg, h, fw, h, Nn);
        }
    }

    // ---- global mean pool ----
    zero_k<<<(Gg * Hh / 4 + TB - 1) / TB, TB>>>((float4*)pool, Gg * Hh / 4);
    zero_k<<<(Gg / 4 + TB - 1) / TB, TB>>>((float4*)cnt, Gg / 4);
    {
        int warps = (Nn + PR - 1) / PR;
        pool_k<<<(warps * 32 + TB - 1) / TB, TB>>>(h, batch, pool);
    }
    cnt_k<<<((Nn + 31) / 32 + TB - 1) / TB, TB>>>(batch, cnt);
    div_k<<<(Gg * Hh + TB - 1) / TB, TB>>>(pool, cnt);

    // ---- classifier head (fc0 + fc1 fused) ----
    {
        FusedW fw;
        fw.wh[0] = wth + woff(9);  fw.wl[0] = wtl + woff(9);
        fw.wh[1] = wth + woff(10); fw.wl[1] = wtl + woff(10);
        fw.wh[2] = nullptr;        fw.wl[2] = nullptr;
        fw.b[0] = fc0b; fw.b[1] = fc1b; fw.b[2] = nullptr;
        fused_mlp<Hh, 2, 0><<<hgrid, 256, SMEM_FUSED>>>(pool, nullptr, fw, hd2, Gg);
    }
    out_k<<<(Gg + 127) / 128, 128>>>(hd2, outw, outb, (float*)d_out);
}